// round 1
// baseline (speedup 1.0000x reference)
#include <cuda_runtime.h>
#include <math_constants.h>

// Problem constants
#define BATCH 128
#define TLEN  256
#define CDIM  768          // n_embd == head_size
#define MROWS (BATCH * TLEN)   // 32768
#define HALF  (CDIM / 2)       // 384

// Scratch (device-global; no runtime allocation allowed)
__device__ float g_q[(size_t)MROWS * CDIM];
__device__ float g_k[(size_t)MROWS * CDIM];
__device__ float g_v[(size_t)MROWS * CDIM];
__device__ float g_S[(size_t)BATCH * TLEN * TLEN];   // scores -> probabilities (in place)
__device__ float g_cos[TLEN * HALF];
__device__ float g_sin[TLEN * HALF];

// ---------------------------------------------------------------------------
// RoPE tables: cos/sin[t, j], theta_j = 10000^(-2j/768), ang = t * theta_j
// ---------------------------------------------------------------------------
__global__ void rope_table_kernel() {
    int idx = blockIdx.x * blockDim.x + threadIdx.x;   // 0 .. 256*384-1
    if (idx >= TLEN * HALF) return;
    int t = idx / HALF;
    int j = idx % HALF;
    // theta = exp(-2j/768 * ln(10000))
    float theta = expf(-2.0f * (float)j * (1.0f / 768.0f) * 9.210340371976184f);
    float ang = (float)t * theta;
    float s, c;
    sincosf(ang, &s, &c);
    g_cos[idx] = c;
    g_sin[idx] = s;
}

// ---------------------------------------------------------------------------
// Fused QKV GEMM: out = x @ W, with RoPE epilogue for q (z=0) and k (z=1).
// grid = (768/64=12, 32768/64=512, 3), block = 256 threads, 64x64 tile, 4x4/thr
// ---------------------------------------------------------------------------
__global__ void __launch_bounds__(256) qkv_kernel(
    const float* __restrict__ x,
    const float* __restrict__ Wq,
    const float* __restrict__ Wk,
    const float* __restrict__ Wv)
{
    __shared__ float As[16][64];   // [k][m] (transposed scatter)
    __shared__ float Bs[16][64];   // [k][n]

    const int z = blockIdx.z;
    const float* __restrict__ W = (z == 0) ? Wq : ((z == 1) ? Wk : Wv);
    float* __restrict__ outp = (z == 0) ? g_q : ((z == 1) ? g_k : g_v);

    const int bm = blockIdx.y;
    const int bn = blockIdx.x;
    const int tid = threadIdx.x;
    const int tx = tid & 15;
    const int ty = tid >> 4;

    // A load: each thread one float4 along K
    const int a_m = tid >> 2;
    const int a_k = (tid & 3) << 2;
    // B load: each thread one float4 along N
    const int b_k = tid >> 4;
    const int b_n = (tid & 15) << 2;

    const float* a_ptr = x + (size_t)(bm * 64 + a_m) * CDIM + a_k;
    const float* b_ptr = W + (size_t)b_k * CDIM + bn * 64 + b_n;

    float acc[4][4] = {};

    for (int kt = 0; kt < CDIM; kt += 16) {
        float4 av = *(const float4*)(a_ptr + kt);
        float4 bv = *(const float4*)(b_ptr + (size_t)kt * CDIM);
        __syncthreads();
        As[a_k + 0][a_m] = av.x;
        As[a_k + 1][a_m] = av.y;
        As[a_k + 2][a_m] = av.z;
        As[a_k + 3][a_m] = av.w;
        *(float4*)&Bs[b_k][b_n] = bv;
        __syncthreads();
#pragma unroll
        for (int k = 0; k < 16; k++) {
            float4 a = *(const float4*)&As[k][ty << 2];
            float4 b = *(const float4*)&Bs[k][tx << 2];
            acc[0][0] += a.x * b.x; acc[0][1] += a.x * b.y; acc[0][2] += a.x * b.z; acc[0][3] += a.x * b.w;
            acc[1][0] += a.y * b.x; acc[1][1] += a.y * b.y; acc[1][2] += a.y * b.z; acc[1][3] += a.y * b.w;
            acc[2][0] += a.z * b.x; acc[2][1] += a.z * b.y; acc[2][2] += a.z * b.z; acc[2][3] += a.z * b.w;
            acc[3][0] += a.w * b.x; acc[3][1] += a.w * b.y; acc[3][2] += a.w * b.z; acc[3][3] += a.w * b.w;
        }
    }

    const int row0 = bm * 64 + (ty << 2);
    const int col0 = bn * 64 + (tx << 2);

    if (z < 2) {
        // RoPE: pairs (2j, 2j+1); col0 is a multiple of 4 -> two complete pairs
        const int j0 = col0 >> 1;
#pragma unroll
        for (int i = 0; i < 4; i++) {
            int t = (row0 + i) & (TLEN - 1);
            float c0 = g_cos[t * HALF + j0],     s0 = g_sin[t * HALF + j0];
            float c1 = g_cos[t * HALF + j0 + 1], s1 = g_sin[t * HALF + j0 + 1];
            float4 r;
            r.x = acc[i][0] * c0 - acc[i][1] * s0;
            r.y = acc[i][0] * s0 + acc[i][1] * c0;
            r.z = acc[i][2] * c1 - acc[i][3] * s1;
            r.w = acc[i][2] * s1 + acc[i][3] * c1;
            *(float4*)(outp + (size_t)(row0 + i) * CDIM + col0) = r;
        }
    } else {
#pragma unroll
        for (int i = 0; i < 4; i++) {
            float4 r = make_float4(acc[i][0], acc[i][1], acc[i][2], acc[i][3]);
            *(float4*)(outp + (size_t)(row0 + i) * CDIM + col0) = r;
        }
    }
}

// ---------------------------------------------------------------------------
// Scores: S[b,i,j] = scale * dot(q[b,i], k[b,j]).
// grid = (4 jblocks, 4 iblocks, 128 batches). Blocks fully above the causal
// diagonal are skipped (softmax never reads j > i).
// ---------------------------------------------------------------------------
__global__ void __launch_bounds__(256) scores_kernel() {
    const int bj = blockIdx.x;
    const int bi = blockIdx.y;
    if (bj > bi) return;   // entirely masked
    const int b = blockIdx.z;

    __shared__ float As[16][64];   // [d][i]
    __shared__ float Bs[16][64];   // [d][j]

    const float* __restrict__ qp = g_q + (size_t)b * TLEN * CDIM;
    const float* __restrict__ kp = g_k + (size_t)b * TLEN * CDIM;

    const int tid = threadIdx.x;
    const int tx = tid & 15;
    const int ty = tid >> 4;
    const int a_m = tid >> 2;
    const int a_k = (tid & 3) << 2;

    const float* a_ptr = qp + (size_t)(bi * 64 + a_m) * CDIM + a_k;
    const float* b_ptr = kp + (size_t)(bj * 64 + a_m) * CDIM + a_k;

    float acc[4][4] = {};

    for (int kt = 0; kt < CDIM; kt += 16) {
        float4 av = *(const float4*)(a_ptr + kt);
        float4 bv = *(const float4*)(b_ptr + kt);
        __syncthreads();
        As[a_k + 0][a_m] = av.x; As[a_k + 1][a_m] = av.y;
        As[a_k + 2][a_m] = av.z; As[a_k + 3][a_m] = av.w;
        Bs[a_k + 0][a_m] = bv.x; Bs[a_k + 1][a_m] = bv.y;
        Bs[a_k + 2][a_m] = bv.z; Bs[a_k + 3][a_m] = bv.w;
        __syncthreads();
#pragma unroll
        for (int k = 0; k < 16; k++) {
            float4 a = *(const float4*)&As[k][ty << 2];
            float4 b = *(const float4*)&Bs[k][tx << 2];
            acc[0][0] += a.x * b.x; acc[0][1] += a.x * b.y; acc[0][2] += a.x * b.z; acc[0][3] += a.x * b.w;
            acc[1][0] += a.y * b.x; acc[1][1] += a.y * b.y; acc[1][2] += a.y * b.z; acc[1][3] += a.y * b.w;
            acc[2][0] += a.z * b.x; acc[2][1] += a.z * b.y; acc[2][2] += a.z * b.z; acc[2][3] += a.z * b.w;
            acc[3][0] += a.w * b.x; acc[3][1] += a.w * b.y; acc[3][2] += a.w * b.z; acc[3][3] += a.w * b.w;
        }
    }

    const float scale = 0.03608439182435161f;   // 768^-0.5
    float* __restrict__ Sp = g_S + (size_t)b * TLEN * TLEN;
    const int i0 = bi * 64 + (ty << 2);
    const int j0 = bj * 64 + (tx << 2);
#pragma unroll
    for (int i = 0; i < 4; i++) {
        float4 r = make_float4(acc[i][0] * scale, acc[i][1] * scale,
                               acc[i][2] * scale, acc[i][3] * scale);
        *(float4*)(Sp + (size_t)(i0 + i) * TLEN + j0) = r;
    }
}

// ---------------------------------------------------------------------------
// Softmax in place: one warp per (b, i) row. Reads only j <= i, writes full
// row (zeros for j > i) so PV can read a dense [256,256] probability matrix.
// ---------------------------------------------------------------------------
__global__ void __launch_bounds__(256) softmax_kernel() {
    const int gwarp = (blockIdx.x * blockDim.x + threadIdx.x) >> 5;
    const int lane = threadIdx.x & 31;
    const int b = gwarp >> 8;
    const int i = gwarp & 255;

    float* __restrict__ row = g_S + (size_t)b * TLEN * TLEN + (size_t)i * TLEN;

    float v[8];
    float m = -CUDART_INF_F;
#pragma unroll
    for (int r = 0; r < 8; r++) {
        int j = lane + 32 * r;
        v[r] = (j <= i) ? row[j] : -CUDART_INF_F;
        m = fmaxf(m, v[r]);
    }
#pragma unroll
    for (int off = 16; off > 0; off >>= 1)
        m = fmaxf(m, __shfl_xor_sync(0xFFFFFFFFu, m, off));

    float sum = 0.0f;
#pragma unroll
    for (int r = 0; r < 8; r++) {
        float p = expf(v[r] - m);   // expf(-inf) == 0
        v[r] = p;
        sum += p;
    }
#pragma unroll
    for (int off = 16; off > 0; off >>= 1)
        sum += __shfl_xor_sync(0xFFFFFFFFu, sum, off);

    const float inv = 1.0f / sum;
#pragma unroll
    for (int r = 0; r < 8; r++)
        row[lane + 32 * r] = v[r] * inv;
}

// ---------------------------------------------------------------------------
// PV: out[b] = P[b] @ V[b].  grid = (12 nblocks, 4 mblocks, 128 batches).
// Causal truncation: P[i][j] = 0 for j > i, so K-loop stops at (bm+1)*64.
// ---------------------------------------------------------------------------
__global__ void __launch_bounds__(256) pv_kernel(float* __restrict__ out) {
    const int bn = blockIdx.x;
    const int bm = blockIdx.y;
    const int b = blockIdx.z;

    __shared__ float As[16][64];   // [k][i]  (P)
    __shared__ float Bs[16][64];   // [k][n]  (V)

    const float* __restrict__ P = g_S + (size_t)b * TLEN * TLEN;
    const float* __restrict__ V = g_v + (size_t)b * TLEN * CDIM;

    const int tid = threadIdx.x;
    const int tx = tid & 15;
    const int ty = tid >> 4;
    const int a_m = tid >> 2;
    const int a_k = (tid & 3) << 2;
    const int b_k = tid >> 4;
    const int b_n = (tid & 15) << 2;

    const float* a_ptr = P + (size_t)(bm * 64 + a_m) * TLEN + a_k;
    const float* b_ptr = V + (size_t)b_k * CDIM + bn * 64 + b_n;

    float acc[4][4] = {};
    const int kend = (bm + 1) * 64;   // causal: only j < (bm+1)*64 contribute

    for (int kt = 0; kt < kend; kt += 16) {
        float4 av = *(const float4*)(a_ptr + kt);
        float4 bv = *(const float4*)(b_ptr + (size_t)kt * CDIM);
        __syncthreads();
        As[a_k + 0][a_m] = av.x; As[a_k + 1][a_m] = av.y;
        As[a_k + 2][a_m] = av.z; As[a_k + 3][a_m] = av.w;
        *(float4*)&Bs[b_k][b_n] = bv;
        __syncthreads();
#pragma unroll
        for (int k = 0; k < 16; k++) {
            float4 a = *(const float4*)&As[k][ty << 2];
            float4 b = *(const float4*)&Bs[k][tx << 2];
            acc[0][0] += a.x * b.x; acc[0][1] += a.x * b.y; acc[0][2] += a.x * b.z; acc[0][3] += a.x * b.w;
            acc[1][0] += a.y * b.x; acc[1][1] += a.y * b.y; acc[1][2] += a.y * b.z; acc[1][3] += a.y * b.w;
            acc[2][0] += a.z * b.x; acc[2][1] += a.z * b.y; acc[2][2] += a.z * b.z; acc[2][3] += a.z * b.w;
            acc[3][0] += a.w * b.x; acc[3][1] += a.w * b.y; acc[3][2] += a.w * b.z; acc[3][3] += a.w * b.w;
        }
    }

    const int i0 = bm * 64 + (ty << 2);
    const int n0 = bn * 64 + (tx << 2);
    float* __restrict__ op = out + (size_t)b * TLEN * CDIM;
#pragma unroll
    for (int i = 0; i < 4; i++) {
        float4 r = make_float4(acc[i][0], acc[i][1], acc[i][2], acc[i][3]);
        *(float4*)(op + (size_t)(i0 + i) * CDIM + n0) = r;
    }
}

// ---------------------------------------------------------------------------
extern "C" void kernel_launch(void* const* d_in, const int* in_sizes, int n_in,
                              void* d_out, int out_size) {
    const float* x  = (const float*)d_in[0];
    const float* Wq = (const float*)d_in[1];
    const float* Wk = (const float*)d_in[2];
    const float* Wv = (const float*)d_in[3];
    float* out = (float*)d_out;

    rope_table_kernel<<<(TLEN * HALF + 255) / 256, 256>>>();
    qkv_kernel<<<dim3(CDIM / 64, MROWS / 64, 3), 256>>>(x, Wq, Wk, Wv);
    scores_kernel<<<dim3(TLEN / 64, TLEN / 64, BATCH), 256>>>();
    softmax_kernel<<<(MROWS * 32) / 256, 256>>>();
    pv_kernel<<<dim3(CDIM / 64, TLEN / 64, BATCH), 256>>>(out);
}

// round 3
// speedup vs baseline: 3.3171x; 3.3171x over previous
#include <cuda_runtime.h>
#include <math_constants.h>
#include <cstdint>

// Problem constants
#define BATCH 128
#define TLEN  256
#define CDIM  768
#define MROWS (BATCH * TLEN)     // 32768
#define HALF  (CDIM / 2)         // 384

// ---------------------------------------------------------------------------
// Device-global scratch (no runtime allocation allowed)
// ---------------------------------------------------------------------------
__device__ __align__(256) float g_q[(size_t)MROWS * CDIM];
__device__ __align__(256) float g_k[(size_t)MROWS * CDIM];
__device__ __align__(256) float g_v[(size_t)MROWS * CDIM];
__device__ __align__(256) float g_S[(size_t)BATCH * TLEN * TLEN];
__device__ __align__(256) float g_cos[TLEN * HALF];
__device__ __align__(256) float g_sin[TLEN * HALF];

// ---------------------------------------------------------------------------
// TF32 helpers (mma.sync is valid PTX for compute_103 — no sm_103a features)
// ---------------------------------------------------------------------------
__device__ __forceinline__ uint32_t f2tf(float f) {
    uint32_t r;
    asm("cvt.rna.tf32.f32 %0, %1;" : "=r"(r) : "f"(f));
    return r;
}

__device__ __forceinline__ void mma_tf32(float* d, const uint32_t* a, const uint32_t* b) {
    asm volatile(
        "mma.sync.aligned.m16n8k8.row.col.f32.tf32.tf32.f32 "
        "{%0,%1,%2,%3}, {%4,%5,%6,%7}, {%8,%9}, {%0,%1,%2,%3};"
        : "+f"(d[0]), "+f"(d[1]), "+f"(d[2]), "+f"(d[3])
        : "r"(a[0]), "r"(a[1]), "r"(a[2]), "r"(a[3]), "r"(b[0]), "r"(b[1]));
}

// ---------------------------------------------------------------------------
// RoPE tables
// ---------------------------------------------------------------------------
__global__ void rope_table_kernel() {
    int idx = blockIdx.x * blockDim.x + threadIdx.x;
    if (idx >= TLEN * HALF) return;
    int t = idx / HALF;
    int j = idx % HALF;
    float theta = expf(-2.0f * (float)j * (1.0f / 768.0f) * 9.210340371976184f);
    float ang = (float)t * theta;
    float s, c;
    sincosf(ang, &s, &c);
    g_cos[idx] = c;
    g_sin[idx] = s;
}

// ---------------------------------------------------------------------------
// QKV GEMM (tf32 mma): out[z] = x @ W[z], RoPE epilogue for z<2.
// CTA tile 128x128, BK=32, 256 threads, warp tile 64x32 (4x4 m16n8k8).
// grid = (768/128=6, 3, 32768/128=256)
// ---------------------------------------------------------------------------
__global__ void __launch_bounds__(256) qkv_mma_kernel(
    const float* __restrict__ x,
    const float* __restrict__ Wq,
    const float* __restrict__ Wk,
    const float* __restrict__ Wv)
{
    __shared__ uint32_t As[128][36];   // [m][k], tf32 bits
    __shared__ uint32_t Bs[32][132];   // [k][n], tf32 bits

    const int z = blockIdx.y;
    const float* __restrict__ W = (z == 0) ? Wq : ((z == 1) ? Wk : Wv);
    float* __restrict__ outp = (z == 0) ? g_q : ((z == 1) ? g_k : g_v);

    const int m0 = blockIdx.z * 128;
    const int n0 = blockIdx.x * 128;
    const int tid = threadIdx.x;
    const int wid = tid >> 5, lane = tid & 31;
    const int wm = (wid & 1) * 64;
    const int wn = (wid >> 1) * 32;
    const int lr = lane >> 2, lc = lane & 3;

    float acc[4][4][4] = {};

    for (int kt = 0; kt < CDIM / 32; kt++) {
        float4 av[4], bv[4];
#pragma unroll
        for (int i = 0; i < 4; i++) {
            int f = tid + i * 256;
            av[i] = *(const float4*)(x + (size_t)(m0 + (f >> 3)) * CDIM + kt * 32 + (f & 7) * 4);
            bv[i] = *(const float4*)(W + (size_t)(kt * 32 + (f >> 5)) * CDIM + n0 + (f & 31) * 4);
        }
        __syncthreads();
#pragma unroll
        for (int i = 0; i < 4; i++) {
            int f = tid + i * 256;
            int ar = f >> 3, ac = (f & 7) * 4;
            As[ar][ac + 0] = f2tf(av[i].x); As[ar][ac + 1] = f2tf(av[i].y);
            As[ar][ac + 2] = f2tf(av[i].z); As[ar][ac + 3] = f2tf(av[i].w);
            int br = f >> 5, bc = (f & 31) * 4;
            Bs[br][bc + 0] = f2tf(bv[i].x); Bs[br][bc + 1] = f2tf(bv[i].y);
            Bs[br][bc + 2] = f2tf(bv[i].z); Bs[br][bc + 3] = f2tf(bv[i].w);
        }
        __syncthreads();
#pragma unroll
        for (int ks = 0; ks < 4; ks++) {
            uint32_t a[4][4], b[4][2];
#pragma unroll
            for (int mi = 0; mi < 4; mi++) {
                int r = wm + mi * 16 + lr;
                a[mi][0] = As[r][ks * 8 + lc];
                a[mi][1] = As[r + 8][ks * 8 + lc];
                a[mi][2] = As[r][ks * 8 + lc + 4];
                a[mi][3] = As[r + 8][ks * 8 + lc + 4];
            }
#pragma unroll
            for (int ni = 0; ni < 4; ni++) {
                int c = wn + ni * 8 + lr;
                b[ni][0] = Bs[ks * 8 + lc][c];
                b[ni][1] = Bs[ks * 8 + lc + 4][c];
            }
#pragma unroll
            for (int mi = 0; mi < 4; mi++)
#pragma unroll
                for (int ni = 0; ni < 4; ni++)
                    mma_tf32(acc[mi][ni], a[mi], b[ni]);
        }
    }

    // Epilogue: c-frag cols are (2*lc, 2*lc+1) — exactly a RoPE pair.
#pragma unroll
    for (int mi = 0; mi < 4; mi++) {
#pragma unroll
        for (int half = 0; half < 2; half++) {
            int r = m0 + wm + mi * 16 + lr + half * 8;
            int t = r & (TLEN - 1);
#pragma unroll
            for (int ni = 0; ni < 4; ni++) {
                float o0 = acc[mi][ni][half * 2 + 0];
                float o1 = acc[mi][ni][half * 2 + 1];
                int c = n0 + wn + ni * 8 + 2 * lc;
                if (z < 2) {
                    int j = c >> 1;
                    float cs = g_cos[t * HALF + j], sn = g_sin[t * HALF + j];
                    float p0 = o0 * cs - o1 * sn;
                    float p1 = o0 * sn + o1 * cs;
                    o0 = p0; o1 = p1;
                }
                *(float2*)(outp + (size_t)r * CDIM + c) = make_float2(o0, o1);
            }
        }
    }
}

// ---------------------------------------------------------------------------
// Scores (tf32 mma): S[b,i,j] = scale * dot(q[b,i], k[b,j]).
// CTA tile 64x64, BK=32, 128 threads, warp tile 32x32 (2x4 m16n8k8).
// grid = (4, 4, 128), upper-triangular blocks skipped.
// ---------------------------------------------------------------------------
__global__ void __launch_bounds__(128) scores_mma_kernel() {
    const int bj = blockIdx.x;
    const int bi = blockIdx.y;
    if (bj > bi) return;
    const int b = blockIdx.z;

    __shared__ uint32_t Qs[64][36];   // [i][d]
    __shared__ uint32_t Ks[64][36];   // [j][d]

    const float* __restrict__ qp = g_q + (size_t)b * TLEN * CDIM;
    const float* __restrict__ kp = g_k + (size_t)b * TLEN * CDIM;

    const int tid = threadIdx.x;
    const int wid = tid >> 5, lane = tid & 31;
    const int wm = (wid & 1) * 32;
    const int wn = (wid >> 1) * 32;
    const int lr = lane >> 2, lc = lane & 3;

    float acc[2][4][4] = {};

    for (int kt = 0; kt < CDIM / 32; kt++) {
        float4 qv[4], kv[4];
#pragma unroll
        for (int i = 0; i < 4; i++) {
            int f = tid + i * 128;
            qv[i] = *(const float4*)(qp + (size_t)(bi * 64 + (f >> 3)) * CDIM + kt * 32 + (f & 7) * 4);
            kv[i] = *(const float4*)(kp + (size_t)(bj * 64 + (f >> 3)) * CDIM + kt * 32 + (f & 7) * 4);
        }
        __syncthreads();
#pragma unroll
        for (int i = 0; i < 4; i++) {
            int f = tid + i * 128;
            int r = f >> 3, c = (f & 7) * 4;
            Qs[r][c + 0] = f2tf(qv[i].x); Qs[r][c + 1] = f2tf(qv[i].y);
            Qs[r][c + 2] = f2tf(qv[i].z); Qs[r][c + 3] = f2tf(qv[i].w);
            Ks[r][c + 0] = f2tf(kv[i].x); Ks[r][c + 1] = f2tf(kv[i].y);
            Ks[r][c + 2] = f2tf(kv[i].z); Ks[r][c + 3] = f2tf(kv[i].w);
        }
        __syncthreads();
#pragma unroll
        for (int ks = 0; ks < 4; ks++) {
            uint32_t a[2][4], bfr[4][2];
#pragma unroll
            for (int mi = 0; mi < 2; mi++) {
                int r = wm + mi * 16 + lr;
                a[mi][0] = Qs[r][ks * 8 + lc];
                a[mi][1] = Qs[r + 8][ks * 8 + lc];
                a[mi][2] = Qs[r][ks * 8 + lc + 4];
                a[mi][3] = Qs[r + 8][ks * 8 + lc + 4];
            }
#pragma unroll
            for (int ni = 0; ni < 4; ni++) {
                int c = wn + ni * 8 + lr;
                bfr[ni][0] = Ks[c][ks * 8 + lc];
                bfr[ni][1] = Ks[c][ks * 8 + lc + 4];
            }
#pragma unroll
            for (int mi = 0; mi < 2; mi++)
#pragma unroll
                for (int ni = 0; ni < 4; ni++)
                    mma_tf32(acc[mi][ni], a[mi], bfr[ni]);
        }
    }

    const float scale = 0.03608439182435161f;   // 768^-0.5
    float* __restrict__ Sp = g_S + (size_t)b * TLEN * TLEN;
#pragma unroll
    for (int mi = 0; mi < 2; mi++)
#pragma unroll
        for (int half = 0; half < 2; half++) {
            int r = bi * 64 + wm + mi * 16 + lr + half * 8;
#pragma unroll
            for (int ni = 0; ni < 4; ni++) {
                int c = bj * 64 + wn + ni * 8 + 2 * lc;
                *(float2*)(Sp + (size_t)r * TLEN + c) =
                    make_float2(acc[mi][ni][half * 2] * scale, acc[mi][ni][half * 2 + 1] * scale);
            }
        }
}

// ---------------------------------------------------------------------------
// Softmax in place: one warp per (b, i) row; masks j > i, writes full row.
// ---------------------------------------------------------------------------
__global__ void __launch_bounds__(256) softmax_kernel() {
    const int gwarp = (blockIdx.x * blockDim.x + threadIdx.x) >> 5;
    const int lane = threadIdx.x & 31;
    const int b = gwarp >> 8;
    const int i = gwarp & 255;

    float* __restrict__ row = g_S + (size_t)b * TLEN * TLEN + (size_t)i * TLEN;

    float v[8];
    float m = -CUDART_INF_F;
#pragma unroll
    for (int r = 0; r < 8; r++) {
        int j = lane + 32 * r;
        v[r] = (j <= i) ? row[j] : -CUDART_INF_F;
        m = fmaxf(m, v[r]);
    }
#pragma unroll
    for (int off = 16; off > 0; off >>= 1)
        m = fmaxf(m, __shfl_xor_sync(0xFFFFFFFFu, m, off));

    float sum = 0.0f;
#pragma unroll
    for (int r = 0; r < 8; r++) {
        float p = expf(v[r] - m);
        v[r] = p;
        sum += p;
    }
#pragma unroll
    for (int off = 16; off > 0; off >>= 1)
        sum += __shfl_xor_sync(0xFFFFFFFFu, sum, off);

    const float inv = 1.0f / sum;
#pragma unroll
    for (int r = 0; r < 8; r++)
        row[lane + 32 * r] = v[r] * inv;
}

// ---------------------------------------------------------------------------
// PV (tf32 mma): out[b] = P[b] @ V[b], causal K truncation.
// CTA tile 64x64, BK=32, 128 threads. grid = (12, 4, 128).
// ---------------------------------------------------------------------------
__global__ void __launch_bounds__(128) pv_mma_kernel(float* __restrict__ out) {
    const int bn = blockIdx.x;
    const int bm = blockIdx.y;
    const int b = blockIdx.z;

    __shared__ uint32_t Ps[64][36];   // [i][j]
    __shared__ uint32_t Vs[32][72];   // [j][n]

    const float* __restrict__ P = g_S + (size_t)b * TLEN * TLEN;
    const float* __restrict__ V = g_v + (size_t)b * TLEN * CDIM;

    const int tid = threadIdx.x;
    const int wid = tid >> 5, lane = tid & 31;
    const int wm = (wid & 1) * 32;
    const int wn = (wid >> 1) * 32;
    const int lr = lane >> 2, lc = lane & 3;

    float acc[2][4][4] = {};
    const int nchunk = (bm + 1) * 2;   // causal: j < (bm+1)*64

    for (int kt = 0; kt < nchunk; kt++) {
        float4 pv[4], vv[4];
#pragma unroll
        for (int i = 0; i < 4; i++) {
            int f = tid + i * 128;
            pv[i] = *(const float4*)(P + (size_t)(bm * 64 + (f >> 3)) * TLEN + kt * 32 + (f & 7) * 4);
            vv[i] = *(const float4*)(V + (size_t)(kt * 32 + (f >> 4)) * CDIM + bn * 64 + (f & 15) * 4);
        }
        __syncthreads();
#pragma unroll
        for (int i = 0; i < 4; i++) {
            int f = tid + i * 128;
            int pr = f >> 3, pc = (f & 7) * 4;
            Ps[pr][pc + 0] = f2tf(pv[i].x); Ps[pr][pc + 1] = f2tf(pv[i].y);
            Ps[pr][pc + 2] = f2tf(pv[i].z); Ps[pr][pc + 3] = f2tf(pv[i].w);
            int vr = f >> 4, vc = (f & 15) * 4;
            Vs[vr][vc + 0] = f2tf(vv[i].x); Vs[vr][vc + 1] = f2tf(vv[i].y);
            Vs[vr][vc + 2] = f2tf(vv[i].z); Vs[vr][vc + 3] = f2tf(vv[i].w);
        }
        __syncthreads();
#pragma unroll
        for (int ks = 0; ks < 4; ks++) {
            uint32_t a[2][4], bfr[4][2];
#pragma unroll
            for (int mi = 0; mi < 2; mi++) {
                int r = wm + mi * 16 + lr;
                a[mi][0] = Ps[r][ks * 8 + lc];
                a[mi][1] = Ps[r + 8][ks * 8 + lc];
                a[mi][2] = Ps[r][ks * 8 + lc + 4];
                a[mi][3] = Ps[r + 8][ks * 8 + lc + 4];
            }
#pragma unroll
            for (int ni = 0; ni < 4; ni++) {
                int c = wn + ni * 8 + lr;
                bfr[ni][0] = Vs[ks * 8 + lc][c];
                bfr[ni][1] = Vs[ks * 8 + lc + 4][c];
            }
#pragma unroll
            for (int mi = 0; mi < 2; mi++)
#pragma unroll
                for (int ni = 0; ni < 4; ni++)
                    mma_tf32(acc[mi][ni], a[mi], bfr[ni]);
        }
    }

    float* __restrict__ op = out + (size_t)b * TLEN * CDIM;
#pragma unroll
    for (int mi = 0; mi < 2; mi++)
#pragma unroll
        for (int half = 0; half < 2; half++) {
            int r = bm * 64 + wm + mi * 16 + lr + half * 8;
#pragma unroll
            for (int ni = 0; ni < 4; ni++) {
                int c = bn * 64 + wn + ni * 8 + 2 * lc;
                *(float2*)(op + (size_t)r * CDIM + c) =
                    make_float2(acc[mi][ni][half * 2], acc[mi][ni][half * 2 + 1]);
            }
        }
}

// ---------------------------------------------------------------------------
extern "C" void kernel_launch(void* const* d_in, const int* in_sizes, int n_in,
                              void* d_out, int out_size) {
    const float* x  = (const float*)d_in[0];
    const float* Wq = (const float*)d_in[1];
    const float* Wk = (const float*)d_in[2];
    const float* Wv = (const float*)d_in[3];
    float* out = (float*)d_out;

    rope_table_kernel<<<(TLEN * HALF + 255) / 256, 256>>>();
    qkv_mma_kernel<<<dim3(CDIM / 128, 3, MROWS / 128), 256>>>(x, Wq, Wk, Wv);
    scores_mma_kernel<<<dim3(TLEN / 64, TLEN / 64, BATCH), 128>>>();
    softmax_kernel<<<(MROWS * 32) / 256, 256>>>();
    pv_mma_kernel<<<dim3(CDIM / 64, TLEN / 64, BATCH), 128>>>(out);
}

// round 4
// speedup vs baseline: 3.9288x; 1.1844x over previous
#include <cuda_runtime.h>
#include <math_constants.h>
#include <cstdint>

// Problem constants
#define BATCH 128
#define TLEN  256
#define CDIM  768
#define MROWS (BATCH * TLEN)     // 32768
#define HALF  (CDIM / 2)         // 384

// ---------------------------------------------------------------------------
// Device-global scratch (tf32 bit arrays are k-permuted within 8-groups:
// pos(k) = ((k&3)<<1) | ((k>>2)&1), so mma pairs (lc, lc+4) are adjacent)
// ---------------------------------------------------------------------------
__device__ __align__(256) uint32_t g_xt[(size_t)MROWS * CDIM];          // x, tf32 perm
__device__ __align__(256) uint32_t g_wt[(size_t)3 * CDIM * CDIM];       // W^T [z][n][k], tf32 perm
__device__ __align__(256) uint32_t g_qt[(size_t)MROWS * CDIM];          // q (RoPE'd), tf32 perm
__device__ __align__(256) uint32_t g_kt[(size_t)MROWS * CDIM];          // k (RoPE'd), tf32 perm
__device__ __align__(256) float    g_v[(size_t)MROWS * CDIM];           // v, fp32
__device__ __align__(256) float    g_S[(size_t)BATCH * TLEN * TLEN];
__device__ __align__(256) float    g_cos[TLEN * HALF];
__device__ __align__(256) float    g_sin[TLEN * HALF];

// ---------------------------------------------------------------------------
// Helpers
// ---------------------------------------------------------------------------
__device__ __forceinline__ uint32_t f2tf(float f) {
    uint32_t r;
    asm("cvt.rna.tf32.f32 %0, %1;" : "=r"(r) : "f"(f));
    return r;
}
__device__ __forceinline__ uint32_t smem_u32(const void* p) {
    uint32_t a;
    asm("{ .reg .u64 t; cvta.to.shared.u64 t, %1; cvt.u32.u64 %0, t; }" : "=r"(a) : "l"(p));
    return a;
}
#define CP16(dst, src) asm volatile("cp.async.cg.shared.global [%0], [%1], 16;" :: "r"(dst), "l"(src))
#define CP_COMMIT()    asm volatile("cp.async.commit_group;" ::: "memory")
#define CP_WAIT1()     asm volatile("cp.async.wait_group 1;" ::: "memory")
#define CP_WAIT0()     asm volatile("cp.async.wait_group 0;" ::: "memory")

__device__ __forceinline__ void mma_tf32(float* d, const uint32_t* a, const uint32_t* b) {
    asm volatile(
        "mma.sync.aligned.m16n8k8.row.col.f32.tf32.tf32.f32 "
        "{%0,%1,%2,%3}, {%4,%5,%6,%7}, {%8,%9}, {%0,%1,%2,%3};"
        : "+f"(d[0]), "+f"(d[1]), "+f"(d[2]), "+f"(d[3])
        : "r"(a[0]), "r"(a[1]), "r"(a[2]), "r"(a[3]), "r"(b[0]), "r"(b[1]));
}

__device__ __forceinline__ int kperm(int k) {       // permute within 8-group
    return (k & ~7) | (((k & 3) << 1) | ((k >> 2) & 1));
}

// ---------------------------------------------------------------------------
// RoPE tables
// ---------------------------------------------------------------------------
__global__ void rope_table_kernel() {
    int idx = blockIdx.x * blockDim.x + threadIdx.x;
    if (idx >= TLEN * HALF) return;
    int t = idx / HALF;
    int j = idx % HALF;
    float theta = expf(-2.0f * (float)j * (1.0f / 768.0f) * 9.210340371976184f);
    float ang = (float)t * theta;
    float s, c;
    sincosf(ang, &s, &c);
    g_cos[idx] = c;
    g_sin[idx] = s;
}

// ---------------------------------------------------------------------------
// Convert x -> tf32 bits, k-permuted. One thread per 8 consecutive k.
// ---------------------------------------------------------------------------
__global__ void convert_x_kernel(const float* __restrict__ x) {
    size_t base = ((size_t)blockIdx.x * blockDim.x + threadIdx.x) * 8;
    float4 v0 = *(const float4*)(x + base);
    float4 v1 = *(const float4*)(x + base + 4);
    uint4 o0 = make_uint4(f2tf(v0.x), f2tf(v1.x), f2tf(v0.y), f2tf(v1.y));
    uint4 o1 = make_uint4(f2tf(v0.z), f2tf(v1.z), f2tf(v0.w), f2tf(v1.w));
    *(uint4*)(g_xt + base) = o0;
    *(uint4*)(g_xt + base + 4) = o1;
}

// ---------------------------------------------------------------------------
// Convert W -> W^T [n][k], tf32 bits, k-permuted.
// ---------------------------------------------------------------------------
__global__ void convert_w_kernel(const float* __restrict__ Wq,
                                 const float* __restrict__ Wk,
                                 const float* __restrict__ Wv) {
    __shared__ float tile[32][33];
    int z = blockIdx.z;
    const float* W = (z == 0) ? Wq : ((z == 1) ? Wk : Wv);
    int nb = blockIdx.x * 32, kb = blockIdx.y * 32;
    int tx = threadIdx.x, ty = threadIdx.y;  // 32 x 8
#pragma unroll
    for (int r = 0; r < 32; r += 8)
        tile[ty + r][tx] = W[(size_t)(kb + ty + r) * CDIM + nb + tx];
    __syncthreads();
    uint32_t* outw = g_wt + (size_t)z * CDIM * CDIM;
#pragma unroll
    for (int r = 0; r < 32; r += 8) {
        int n = nb + ty + r;
        int k = kb + tx;
        outw[(size_t)n * CDIM + kperm(k)] = f2tf(tile[tx][ty + r]);
    }
}

// ---------------------------------------------------------------------------
// QKV GEMM (tf32 mma, cp.async double-buffer, LDS.64 fragments).
// CTA 128x128, BK=32, 256 threads, warp tile 64x32.
// grid = (768/128=6, 3, 32768/128=256)
// ---------------------------------------------------------------------------
#define ASTR 40                        // words per smem row (conflict-free LDS.64)
#define AWORDS (128 * ASTR)            // 5120 words per tile
#define QBUF (2 * AWORDS)              // A + B per buffer (words)
#define QSMEM (2 * QBUF * 4)           // 81920 bytes

__global__ void __launch_bounds__(256) qkv_mma_kernel(const float* dummy) {
    extern __shared__ uint32_t sm[];
    const int z = blockIdx.y;
    const int m0 = blockIdx.z * 128;
    const int n0 = blockIdx.x * 128;
    const int tid = threadIdx.x;
    const int wid = tid >> 5, lane = tid & 31;
    const int wm = (wid & 1) * 64;
    const int wn = (wid >> 1) * 32;
    const int lr = lane >> 2, lc = lane & 3;

    const uint32_t* __restrict__ ga = g_xt + (size_t)m0 * CDIM;
    const uint32_t* __restrict__ gb = g_wt + (size_t)z * CDIM * CDIM + (size_t)n0 * CDIM;
    const uint32_t sbase = smem_u32(sm);

    const int ldr = tid >> 3;          // 0..31 row-pair base (x4 iters -> 128 rows)
    const int ldc = (tid & 7) * 4;     // word offset within 32-word chunk

    float acc[4][4][4] = {};

    // prologue: tile 0 -> buf 0
#pragma unroll
    for (int i = 0; i < 4; i++) {
        int r = ldr + i * 32;
        CP16(sbase + (r * ASTR + ldc) * 4, ga + (size_t)r * CDIM + ldc);
        CP16(sbase + (AWORDS + r * ASTR + ldc) * 4, gb + (size_t)r * CDIM + ldc);
    }
    CP_COMMIT();

    for (int kt = 0; kt < CDIM / 32; kt++) {
        if (kt + 1 < CDIM / 32) {
            uint32_t dbase = sbase + ((kt + 1) & 1) * QBUF * 4;
            const uint32_t* gak = ga + (kt + 1) * 32;
            const uint32_t* gbk = gb + (kt + 1) * 32;
#pragma unroll
            for (int i = 0; i < 4; i++) {
                int r = ldr + i * 32;
                CP16(dbase + (r * ASTR + ldc) * 4, gak + (size_t)r * CDIM + ldc);
                CP16(dbase + (AWORDS + r * ASTR + ldc) * 4, gbk + (size_t)r * CDIM + ldc);
            }
            CP_COMMIT();
            CP_WAIT1();
        } else {
            CP_WAIT0();
        }
        __syncthreads();

        const uint32_t* As = sm + (kt & 1) * QBUF;
        const uint32_t* Bs = As + AWORDS;
#pragma unroll
        for (int ks = 0; ks < 4; ks++) {
            uint32_t a[4][4], b[4][2];
#pragma unroll
            for (int mi = 0; mi < 4; mi++) {
                int r = wm + mi * 16 + lr;
                uint2 p = *(const uint2*)(As + r * ASTR + ks * 8 + 2 * lc);
                uint2 q = *(const uint2*)(As + (r + 8) * ASTR + ks * 8 + 2 * lc);
                a[mi][0] = p.x; a[mi][1] = q.x; a[mi][2] = p.y; a[mi][3] = q.y;
            }
#pragma unroll
            for (int ni = 0; ni < 4; ni++) {
                uint2 bb = *(const uint2*)(Bs + (wn + ni * 8 + lr) * ASTR + ks * 8 + 2 * lc);
                b[ni][0] = bb.x; b[ni][1] = bb.y;
            }
#pragma unroll
            for (int mi = 0; mi < 4; mi++)
#pragma unroll
                for (int ni = 0; ni < 4; ni++)
                    mma_tf32(acc[mi][ni], a[mi], b[ni]);
        }
        __syncthreads();
    }

    // Epilogue. z<2: RoPE then write tf32 bits (k-permuted) to g_qt/g_kt.
    // z==2: write fp32 to g_v.
#pragma unroll
    for (int mi = 0; mi < 4; mi++) {
#pragma unroll
        for (int half = 0; half < 2; half++) {
            int r = m0 + wm + mi * 16 + lr + half * 8;
            int t = r & (TLEN - 1);
#pragma unroll
            for (int ni = 0; ni < 4; ni++) {
                float o0 = acc[mi][ni][half * 2 + 0];
                float o1 = acc[mi][ni][half * 2 + 1];
                int c = n0 + wn + ni * 8 + 2 * lc;
                if (z < 2) {
                    int j = c >> 1;
                    float cs = g_cos[t * HALF + j], sn = g_sin[t * HALF + j];
                    float p0 = o0 * cs - o1 * sn;
                    float p1 = o0 * sn + o1 * cs;
                    uint32_t* dst = (z == 0 ? g_qt : g_kt) + (size_t)r * CDIM;
                    dst[kperm(c)] = f2tf(p0);
                    dst[kperm(c + 1)] = f2tf(p1);
                } else {
                    *(float2*)(g_v + (size_t)r * CDIM + c) = make_float2(o0, o1);
                }
            }
        }
    }
}

// ---------------------------------------------------------------------------
// Scores (tf32 mma, cp.async double-buffer, LDS.64 fragments).
// Inputs g_qt/g_kt are tf32 bits, d-permuted. CTA 64x64, BK=32, 128 threads.
// grid = (4, 4, 128), upper-triangular blocks skipped.
// ---------------------------------------------------------------------------
#define SWORDS (64 * ASTR)             // 2560 words per tile
#define SBUF (2 * SWORDS)

__global__ void __launch_bounds__(128) scores_mma_kernel() {
    __shared__ uint32_t sm[2 * SBUF];  // 40960 bytes
    const int bj = blockIdx.x;
    const int bi = blockIdx.y;
    if (bj > bi) return;
    const int b = blockIdx.z;

    const uint32_t* __restrict__ gq = g_qt + ((size_t)b * TLEN + bi * 64) * CDIM;
    const uint32_t* __restrict__ gk = g_kt + ((size_t)b * TLEN + bj * 64) * CDIM;
    const uint32_t sbase = smem_u32(sm);

    const int tid = threadIdx.x;
    const int wid = tid >> 5, lane = tid & 31;
    const int wm = (wid & 1) * 32;
    const int wn = (wid >> 1) * 32;
    const int lr = lane >> 2, lc = lane & 3;

    const int ldr = tid >> 3;          // 0..15 (x4 iters -> 64 rows)
    const int ldc = (tid & 7) * 4;

    float acc[2][4][4] = {};

#pragma unroll
    for (int i = 0; i < 4; i++) {
        int r = ldr + i * 16;
        CP16(sbase + (r * ASTR + ldc) * 4, gq + (size_t)r * CDIM + ldc);
        CP16(sbase + (SWORDS + r * ASTR + ldc) * 4, gk + (size_t)r * CDIM + ldc);
    }
    CP_COMMIT();

    for (int kt = 0; kt < CDIM / 32; kt++) {
        if (kt + 1 < CDIM / 32) {
            uint32_t dbase = sbase + ((kt + 1) & 1) * SBUF * 4;
            const uint32_t* gqk = gq + (kt + 1) * 32;
            const uint32_t* gkk = gk + (kt + 1) * 32;
#pragma unroll
            for (int i = 0; i < 4; i++) {
                int r = ldr + i * 16;
                CP16(dbase + (r * ASTR + ldc) * 4, gqk + (size_t)r * CDIM + ldc);
                CP16(dbase + (SWORDS + r * ASTR + ldc) * 4, gkk + (size_t)r * CDIM + ldc);
            }
            CP_COMMIT();
            CP_WAIT1();
        } else {
            CP_WAIT0();
        }
        __syncthreads();

        const uint32_t* Qs = sm + (kt & 1) * SBUF;
        const uint32_t* Ks = Qs + SWORDS;
#pragma unroll
        for (int ks = 0; ks < 4; ks++) {
            uint32_t a[2][4], bfr[4][2];
#pragma unroll
            for (int mi = 0; mi < 2; mi++) {
                int r = wm + mi * 16 + lr;
                uint2 p = *(const uint2*)(Qs + r * ASTR + ks * 8 + 2 * lc);
                uint2 q = *(const uint2*)(Qs + (r + 8) * ASTR + ks * 8 + 2 * lc);
                a[mi][0] = p.x; a[mi][1] = q.x; a[mi][2] = p.y; a[mi][3] = q.y;
            }
#pragma unroll
            for (int ni = 0; ni < 4; ni++) {
                uint2 bb = *(const uint2*)(Ks + (wn + ni * 8 + lr) * ASTR + ks * 8 + 2 * lc);
                bfr[ni][0] = bb.x; bfr[ni][1] = bb.y;
            }
#pragma unroll
            for (int mi = 0; mi < 2; mi++)
#pragma unroll
                for (int ni = 0; ni < 4; ni++)
                    mma_tf32(acc[mi][ni], a[mi], bfr[ni]);
        }
        __syncthreads();
    }

    const float scale = 0.03608439182435161f;   // 768^-0.5
    float* __restrict__ Sp = g_S + (size_t)b * TLEN * TLEN;
#pragma unroll
    for (int mi = 0; mi < 2; mi++)
#pragma unroll
        for (int half = 0; half < 2; half++) {
            int r = bi * 64 + wm + mi * 16 + lr + half * 8;
#pragma unroll
            for (int ni = 0; ni < 4; ni++) {
                int c = bj * 64 + wn + ni * 8 + 2 * lc;
                *(float2*)(Sp + (size_t)r * TLEN + c) =
                    make_float2(acc[mi][ni][half * 2] * scale, acc[mi][ni][half * 2 + 1] * scale);
            }
        }
}

// ---------------------------------------------------------------------------
// Softmax in place: one warp per (b, i) row; masks j > i, writes full row.
// ---------------------------------------------------------------------------
__global__ void __launch_bounds__(256) softmax_kernel() {
    const int gwarp = (blockIdx.x * blockDim.x + threadIdx.x) >> 5;
    const int lane = threadIdx.x & 31;
    const int b = gwarp >> 8;
    const int i = gwarp & 255;

    float* __restrict__ row = g_S + (size_t)b * TLEN * TLEN + (size_t)i * TLEN;

    float v[8];
    float m = -CUDART_INF_F;
#pragma unroll
    for (int r = 0; r < 8; r++) {
        int j = lane + 32 * r;
        v[r] = (j <= i) ? row[j] : -CUDART_INF_F;
        m = fmaxf(m, v[r]);
    }
#pragma unroll
    for (int off = 16; off > 0; off >>= 1)
        m = fmaxf(m, __shfl_xor_sync(0xFFFFFFFFu, m, off));

    float sum = 0.0f;
#pragma unroll
    for (int r = 0; r < 8; r++) {
        float p = expf(v[r] - m);
        v[r] = p;
        sum += p;
    }
#pragma unroll
    for (int off = 16; off > 0; off >>= 1)
        sum += __shfl_xor_sync(0xFFFFFFFFu, sum, off);

    const float inv = 1.0f / sum;
#pragma unroll
    for (int r = 0; r < 8; r++)
        row[lane + 32 * r] = v[r] * inv;
}

// ---------------------------------------------------------------------------
// PV (tf32 mma): out[b] = P[b] @ V[b], causal K truncation. (R3 form)
// CTA 64x64, BK=32, 128 threads. grid = (12, 4, 128).
// ---------------------------------------------------------------------------
__global__ void __launch_bounds__(128) pv_mma_kernel(float* __restrict__ out) {
    const int bn = blockIdx.x;
    const int bm = blockIdx.y;
    const int b = blockIdx.z;

    __shared__ uint32_t Ps[64][36];
    __shared__ uint32_t Vs[32][72];

    const float* __restrict__ P = g_S + (size_t)b * TLEN * TLEN;
    const float* __restrict__ V = g_v + (size_t)b * TLEN * CDIM;

    const int tid = threadIdx.x;
    const int wid = tid >> 5, lane = tid & 31;
    const int wm = (wid & 1) * 32;
    const int wn = (wid >> 1) * 32;
    const int lr = lane >> 2, lc = lane & 3;

    float acc[2][4][4] = {};
    const int nchunk = (bm + 1) * 2;

    for (int kt = 0; kt < nchunk; kt++) {
        float4 pv[4], vv[4];
#pragma unroll
        for (int i = 0; i < 4; i++) {
            int f = tid + i * 128;
            pv[i] = *(const float4*)(P + (size_t)(bm * 64 + (f >> 3)) * TLEN + kt * 32 + (f & 7) * 4);
            vv[i] = *(const float4*)(V + (size_t)(kt * 32 + (f >> 4)) * CDIM + bn * 64 + (f & 15) * 4);
        }
        __syncthreads();
#pragma unroll
        for (int i = 0; i < 4; i++) {
            int f = tid + i * 128;
            int pr = f >> 3, pc = (f & 7) * 4;
            Ps[pr][pc + 0] = f2tf(pv[i].x); Ps[pr][pc + 1] = f2tf(pv[i].y);
            Ps[pr][pc + 2] = f2tf(pv[i].z); Ps[pr][pc + 3] = f2tf(pv[i].w);
            int vr = f >> 4, vc = (f & 15) * 4;
            Vs[vr][vc + 0] = f2tf(vv[i].x); Vs[vr][vc + 1] = f2tf(vv[i].y);
            Vs[vr][vc + 2] = f2tf(vv[i].z); Vs[vr][vc + 3] = f2tf(vv[i].w);
        }
        __syncthreads();
#pragma unroll
        for (int ks = 0; ks < 4; ks++) {
            uint32_t a[2][4], bfr[4][2];
#pragma unroll
            for (int mi = 0; mi < 2; mi++) {
                int r = wm + mi * 16 + lr;
                a[mi][0] = Ps[r][ks * 8 + lc];
                a[mi][1] = Ps[r + 8][ks * 8 + lc];
                a[mi][2] = Ps[r][ks * 8 + lc + 4];
                a[mi][3] = Ps[r + 8][ks * 8 + lc + 4];
            }
#pragma unroll
            for (int ni = 0; ni < 4; ni++) {
                int c = wn + ni * 8 + lr;
                bfr[ni][0] = Vs[ks * 8 + lc][c];
                bfr[ni][1] = Vs[ks * 8 + lc + 4][c];
            }
#pragma unroll
            for (int mi = 0; mi < 2; mi++)
#pragma unroll
                for (int ni = 0; ni < 4; ni++)
                    mma_tf32(acc[mi][ni], a[mi], bfr[ni]);
        }
    }

    float* __restrict__ op = out + (size_t)b * TLEN * CDIM;
#pragma unroll
    for (int mi = 0; mi < 2; mi++)
#pragma unroll
        for (int half = 0; half < 2; half++) {
            int r = bm * 64 + wm + mi * 16 + lr + half * 8;
#pragma unroll
            for (int ni = 0; ni < 4; ni++) {
                int c = bn * 64 + wn + ni * 8 + 2 * lc;
                *(float2*)(op + (size_t)r * CDIM + c) =
                    make_float2(acc[mi][ni][half * 2], acc[mi][ni][half * 2 + 1]);
            }
        }
}

// ---------------------------------------------------------------------------
extern "C" void kernel_launch(void* const* d_in, const int* in_sizes, int n_in,
                              void* d_out, int out_size) {
    const float* x  = (const float*)d_in[0];
    const float* Wq = (const float*)d_in[1];
    const float* Wk = (const float*)d_in[2];
    const float* Wv = (const float*)d_in[3];
    float* out = (float*)d_out;

    cudaFuncSetAttribute(qkv_mma_kernel, cudaFuncAttributeMaxDynamicSharedMemorySize, QSMEM);

    rope_table_kernel<<<(TLEN * HALF + 255) / 256, 256>>>();
    convert_x_kernel<<<(int)((size_t)MROWS * CDIM / 8 / 256), 256>>>(x);
    convert_w_kernel<<<dim3(CDIM / 32, CDIM / 32, 3), dim3(32, 8)>>>(Wq, Wk, Wv);
    qkv_mma_kernel<<<dim3(CDIM / 128, 3, MROWS / 128), 256, QSMEM>>>(x);
    scores_mma_kernel<<<dim3(TLEN / 64, TLEN / 64, BATCH), 128>>>();
    softmax_kernel<<<(MROWS * 32) / 256, 256>>>();
    pv_mma_kernel<<<dim3(CDIM / 64, TLEN / 64, BATCH), 128>>>(out);
}

// round 5
// speedup vs baseline: 4.3830x; 1.1156x over previous
#include <cuda_runtime.h>
#include <math_constants.h>
#include <cstdint>

// Problem constants
#define BATCH 128
#define TLEN  256
#define CDIM  768
#define MROWS (BATCH * TLEN)     // 32768
#define HALF  (CDIM / 2)         // 384

// ---------------------------------------------------------------------------
// Device-global scratch (tf32 bit arrays are k-permuted within 8-groups:
// pos(k) = ((k&3)<<1) | ((k>>2)&1), so mma pairs (lc, lc+4) are adjacent)
// ---------------------------------------------------------------------------
__device__ __align__(256) uint32_t g_xt[(size_t)MROWS * CDIM];          // x, tf32 perm
__device__ __align__(256) uint32_t g_wt[(size_t)3 * CDIM * CDIM];       // W^T [z][n][k], tf32 perm
__device__ __align__(256) uint32_t g_qt[(size_t)MROWS * CDIM];          // q (RoPE'd), tf32 perm
__device__ __align__(256) uint32_t g_kt[(size_t)MROWS * CDIM];          // k (RoPE'd), tf32 perm
__device__ __align__(256) float    g_v[(size_t)MROWS * CDIM];           // v, fp32
__device__ __align__(256) float    g_S[(size_t)BATCH * TLEN * TLEN];
__device__ __align__(256) float    g_cos[TLEN * HALF];
__device__ __align__(256) float    g_sin[TLEN * HALF];

// ---------------------------------------------------------------------------
// Helpers
// ---------------------------------------------------------------------------
__device__ __forceinline__ uint32_t f2tf(float f) {
    uint32_t r;
    asm("cvt.rna.tf32.f32 %0, %1;" : "=r"(r) : "f"(f));
    return r;
}
__device__ __forceinline__ uint32_t smem_u32(const void* p) {
    uint32_t a;
    asm("{ .reg .u64 t; cvta.to.shared.u64 t, %1; cvt.u32.u64 %0, t; }" : "=r"(a) : "l"(p));
    return a;
}
#define CP16(dst, src) asm volatile("cp.async.cg.shared.global [%0], [%1], 16;" :: "r"(dst), "l"(src))
#define CP_COMMIT()    asm volatile("cp.async.commit_group;" ::: "memory")
#define CP_WAIT1()     asm volatile("cp.async.wait_group 1;" ::: "memory")
#define CP_WAIT0()     asm volatile("cp.async.wait_group 0;" ::: "memory")

__device__ __forceinline__ void mma_tf32(float* d, const uint32_t* a, const uint32_t* b) {
    asm volatile(
        "mma.sync.aligned.m16n8k8.row.col.f32.tf32.tf32.f32 "
        "{%0,%1,%2,%3}, {%4,%5,%6,%7}, {%8,%9}, {%0,%1,%2,%3};"
        : "+f"(d[0]), "+f"(d[1]), "+f"(d[2]), "+f"(d[3])
        : "r"(a[0]), "r"(a[1]), "r"(a[2]), "r"(a[3]), "r"(b[0]), "r"(b[1]));
}

__device__ __forceinline__ int kperm(int k) {       // permute within 8-group
    return (k & ~7) | (((k & 3) << 1) | ((k >> 2) & 1));
}

// ---------------------------------------------------------------------------
// RoPE tables
// ---------------------------------------------------------------------------
__global__ void rope_table_kernel() {
    int idx = blockIdx.x * blockDim.x + threadIdx.x;
    if (idx >= TLEN * HALF) return;
    int t = idx / HALF;
    int j = idx % HALF;
    float theta = expf(-2.0f * (float)j * (1.0f / 768.0f) * 9.210340371976184f);
    float ang = (float)t * theta;
    float s, c;
    sincosf(ang, &s, &c);
    g_cos[idx] = c;
    g_sin[idx] = s;
}

// ---------------------------------------------------------------------------
// Convert x -> tf32 bits, k-permuted. One thread per 8 consecutive k.
// ---------------------------------------------------------------------------
__global__ void convert_x_kernel(const float* __restrict__ x) {
    size_t base = ((size_t)blockIdx.x * blockDim.x + threadIdx.x) * 8;
    float4 v0 = *(const float4*)(x + base);
    float4 v1 = *(const float4*)(x + base + 4);
    uint4 o0 = make_uint4(f2tf(v0.x), f2tf(v1.x), f2tf(v0.y), f2tf(v1.y));
    uint4 o1 = make_uint4(f2tf(v0.z), f2tf(v1.z), f2tf(v0.w), f2tf(v1.w));
    *(uint4*)(g_xt + base) = o0;
    *(uint4*)(g_xt + base + 4) = o1;
}

// ---------------------------------------------------------------------------
// Convert W -> W^T [n][k], tf32 bits, k-permuted.
// ---------------------------------------------------------------------------
__global__ void convert_w_kernel(const float* __restrict__ Wq,
                                 const float* __restrict__ Wk,
                                 const float* __restrict__ Wv) {
    __shared__ float tile[32][33];
    int z = blockIdx.z;
    const float* W = (z == 0) ? Wq : ((z == 1) ? Wk : Wv);
    int nb = blockIdx.x * 32, kb = blockIdx.y * 32;
    int tx = threadIdx.x, ty = threadIdx.y;  // 32 x 8
#pragma unroll
    for (int r = 0; r < 32; r += 8)
        tile[ty + r][tx] = W[(size_t)(kb + ty + r) * CDIM + nb + tx];
    __syncthreads();
    uint32_t* outw = g_wt + (size_t)z * CDIM * CDIM;
#pragma unroll
    for (int r = 0; r < 32; r += 8) {
        int n = nb + ty + r;
        int k = kb + tx;
        outw[(size_t)n * CDIM + kperm(k)] = f2tf(tile[tx][ty + r]);
    }
}

// ---------------------------------------------------------------------------
// QKV GEMM (tf32 mma, 3-stage cp.async, XOR-swizzled smem, 1 sync/iter).
// CTA 128x128, BK=32, 256 threads, warp tile 64x32.
// smem tile: 128 rows x 32 words, word = r*32 + 8*((c>>3)^(r&3)) + (c&7)
// grid = (768/128=6, 3, 32768/128=256)
// ---------------------------------------------------------------------------
#define TWORDS (128 * 32)              // 4096 words per operand tile
#define STGW   (2 * TWORDS)            // A + B per stage (words) = 8192
#define NSTG   3
#define QSMEM  (NSTG * STGW * 4)       // 98304 bytes
#define NKT    (CDIM / 32)             // 24

__device__ __forceinline__ void qkv_load_stage(uint32_t dst, const uint32_t* __restrict__ gak,
                                               const uint32_t* __restrict__ gbk, int tid) {
    const int r0 = tid >> 3;
    const int cb = (tid & 7) * 4;      // 0,4,...,28; granule cb>>3, offset cb&7 in {0,4}
#pragma unroll
    for (int i = 0; i < 4; i++) {
        int r = r0 + i * 32;
        uint32_t sw = (uint32_t)(r * 32 + (((cb >> 3) ^ (r & 3)) << 3) + (cb & 7)) * 4;
        CP16(dst + sw, gak + (size_t)r * CDIM + cb);
        CP16(dst + TWORDS * 4 + sw, gbk + (size_t)r * CDIM + cb);
    }
    CP_COMMIT();
}

__global__ void __launch_bounds__(256, 2) qkv_mma_kernel(const float* dummy) {
    extern __shared__ uint32_t sm[];
    const int z = blockIdx.y;
    const int m0 = blockIdx.z * 128;
    const int n0 = blockIdx.x * 128;
    const int tid = threadIdx.x;
    const int wid = tid >> 5, lane = tid & 31;
    const int wm = (wid & 1) * 64;
    const int wn = (wid >> 1) * 32;
    const int lr = lane >> 2, lc = lane & 3;
    const int lr3 = lr & 3;

    const uint32_t* __restrict__ ga = g_xt + (size_t)m0 * CDIM;
    const uint32_t* __restrict__ gb = g_wt + (size_t)z * CDIM * CDIM + (size_t)n0 * CDIM;
    const uint32_t sbase = smem_u32(sm);

    float acc[4][4][4] = {};

    // prologue: stages for kt=0,1
    qkv_load_stage(sbase, ga, gb, tid);
    qkv_load_stage(sbase + STGW * 4, ga + 32, gb + 32, tid);

    int cur = 0, wrt = 2;
    for (int kt = 0; kt < NKT; kt++) {
        if (kt == NKT - 1) { CP_WAIT0(); } else { CP_WAIT1(); }
        __syncthreads();

        if (kt + 2 < NKT) {
            qkv_load_stage(sbase + wrt * STGW * 4, ga + (kt + 2) * 32, gb + (kt + 2) * 32, tid);
            wrt = (wrt == 2) ? 0 : wrt + 1;
        }

        const uint32_t* As = sm + cur * STGW;
        const uint32_t* Bs = As + TWORDS;
        cur = (cur == 2) ? 0 : cur + 1;
#pragma unroll
        for (int ks = 0; ks < 4; ks++) {
            const int co = ((ks ^ lr3) << 3) + 2 * lc;   // swizzled col offset
            uint32_t a[4][4], b[4][2];
#pragma unroll
            for (int mi = 0; mi < 4; mi++) {
                int r = wm + mi * 16 + lr;
                uint2 p = *(const uint2*)(As + r * 32 + co);
                uint2 q = *(const uint2*)(As + (r + 8) * 32 + co);
                a[mi][0] = p.x; a[mi][1] = q.x; a[mi][2] = p.y; a[mi][3] = q.y;
            }
#pragma unroll
            for (int ni = 0; ni < 4; ni++) {
                uint2 bb = *(const uint2*)(Bs + (wn + ni * 8 + lr) * 32 + co);
                b[ni][0] = bb.x; b[ni][1] = bb.y;
            }
#pragma unroll
            for (int mi = 0; mi < 4; mi++)
#pragma unroll
                for (int ni = 0; ni < 4; ni++)
                    mma_tf32(acc[mi][ni], a[mi], b[ni]);
        }
    }

    // Epilogue. z<2: RoPE then write tf32 bits (k-permuted) to g_qt/g_kt.
    // z==2: write fp32 to g_v.
#pragma unroll
    for (int mi = 0; mi < 4; mi++) {
#pragma unroll
        for (int half = 0; half < 2; half++) {
            int r = m0 + wm + mi * 16 + lr + half * 8;
            int t = r & (TLEN - 1);
#pragma unroll
            for (int ni = 0; ni < 4; ni++) {
                float o0 = acc[mi][ni][half * 2 + 0];
                float o1 = acc[mi][ni][half * 2 + 1];
                int c = n0 + wn + ni * 8 + 2 * lc;
                if (z < 2) {
                    int j = c >> 1;
                    float cs = g_cos[t * HALF + j], sn = g_sin[t * HALF + j];
                    float p0 = o0 * cs - o1 * sn;
                    float p1 = o0 * sn + o1 * cs;
                    uint32_t* dst = (z == 0 ? g_qt : g_kt) + (size_t)r * CDIM;
                    dst[kperm(c)] = f2tf(p0);
                    dst[kperm(c + 1)] = f2tf(p1);
                } else {
                    *(float2*)(g_v + (size_t)r * CDIM + c) = make_float2(o0, o1);
                }
            }
        }
    }
}

// ---------------------------------------------------------------------------
// Scores (tf32 mma, cp.async double-buffer, LDS.64 fragments, padded layout).
// Inputs g_qt/g_kt are tf32 bits, d-permuted. CTA 64x64, BK=32, 128 threads.
// grid = (4, 4, 128), upper-triangular blocks skipped.
// ---------------------------------------------------------------------------
#define ASTR 40
#define SWORDS (64 * ASTR)             // 2560 words per tile
#define SBUF (2 * SWORDS)

__global__ void __launch_bounds__(128) scores_mma_kernel() {
    __shared__ uint32_t sm[2 * SBUF];  // 40960 bytes
    const int bj = blockIdx.x;
    const int bi = blockIdx.y;
    if (bj > bi) return;
    const int b = blockIdx.z;

    const uint32_t* __restrict__ gq = g_qt + ((size_t)b * TLEN + bi * 64) * CDIM;
    const uint32_t* __restrict__ gk = g_kt + ((size_t)b * TLEN + bj * 64) * CDIM;
    const uint32_t sbase = smem_u32(sm);

    const int tid = threadIdx.x;
    const int wid = tid >> 5, lane = tid & 31;
    const int wm = (wid & 1) * 32;
    const int wn = (wid >> 1) * 32;
    const int lr = lane >> 2, lc = lane & 3;

    const int ldr = tid >> 3;          // 0..15 (x4 iters -> 64 rows)
    const int ldc = (tid & 7) * 4;

    float acc[2][4][4] = {};

#pragma unroll
    for (int i = 0; i < 4; i++) {
        int r = ldr + i * 16;
        CP16(sbase + (r * ASTR + ldc) * 4, gq + (size_t)r * CDIM + ldc);
        CP16(sbase + (SWORDS + r * ASTR + ldc) * 4, gk + (size_t)r * CDIM + ldc);
    }
    CP_COMMIT();

    for (int kt = 0; kt < CDIM / 32; kt++) {
        if (kt + 1 < CDIM / 32) {
            uint32_t dbase = sbase + ((kt + 1) & 1) * SBUF * 4;
            const uint32_t* gqk = gq + (kt + 1) * 32;
            const uint32_t* gkk = gk + (kt + 1) * 32;
#pragma unroll
            for (int i = 0; i < 4; i++) {
                int r = ldr + i * 16;
                CP16(dbase + (r * ASTR + ldc) * 4, gqk + (size_t)r * CDIM + ldc);
                CP16(dbase + (SWORDS + r * ASTR + ldc) * 4, gkk + (size_t)r * CDIM + ldc);
            }
            CP_COMMIT();
            CP_WAIT1();
        } else {
            CP_WAIT0();
        }
        __syncthreads();

        const uint32_t* Qs = sm + (kt & 1) * SBUF;
        const uint32_t* Ks = Qs + SWORDS;
#pragma unroll
        for (int ks = 0; ks < 4; ks++) {
            uint32_t a[2][4], bfr[4][2];
#pragma unroll
            for (int mi = 0; mi < 2; mi++) {
                int r = wm + mi * 16 + lr;
                uint2 p = *(const uint2*)(Qs + r * ASTR + ks * 8 + 2 * lc);
                uint2 q = *(const uint2*)(Qs + (r + 8) * ASTR + ks * 8 + 2 * lc);
                a[mi][0] = p.x; a[mi][1] = q.x; a[mi][2] = p.y; a[mi][3] = q.y;
            }
#pragma unroll
            for (int ni = 0; ni < 4; ni++) {
                uint2 bb = *(const uint2*)(Ks + (wn + ni * 8 + lr) * ASTR + ks * 8 + 2 * lc);
                bfr[ni][0] = bb.x; bfr[ni][1] = bb.y;
            }
#pragma unroll
            for (int mi = 0; mi < 2; mi++)
#pragma unroll
                for (int ni = 0; ni < 4; ni++)
                    mma_tf32(acc[mi][ni], a[mi], bfr[ni]);
        }
        __syncthreads();
    }

    const float scale = 0.03608439182435161f;   // 768^-0.5
    float* __restrict__ Sp = g_S + (size_t)b * TLEN * TLEN;
#pragma unroll
    for (int mi = 0; mi < 2; mi++)
#pragma unroll
        for (int half = 0; half < 2; half++) {
            int r = bi * 64 + wm + mi * 16 + lr + half * 8;
#pragma unroll
            for (int ni = 0; ni < 4; ni++) {
                int c = bj * 64 + wn + ni * 8 + 2 * lc;
                *(float2*)(Sp + (size_t)r * TLEN + c) =
                    make_float2(acc[mi][ni][half * 2] * scale, acc[mi][ni][half * 2 + 1] * scale);
            }
        }
}

// ---------------------------------------------------------------------------
// Softmax in place: one warp per (b, i) row; masks j > i, writes full row.
// ---------------------------------------------------------------------------
__global__ void __launch_bounds__(256) softmax_kernel() {
    const int gwarp = (blockIdx.x * blockDim.x + threadIdx.x) >> 5;
    const int lane = threadIdx.x & 31;
    const int b = gwarp >> 8;
    const int i = gwarp & 255;

    float* __restrict__ row = g_S + (size_t)b * TLEN * TLEN + (size_t)i * TLEN;

    float v[8];
    float m = -CUDART_INF_F;
#pragma unroll
    for (int r = 0; r < 8; r++) {
        int j = lane + 32 * r;
        v[r] = (j <= i) ? row[j] : -CUDART_INF_F;
        m = fmaxf(m, v[r]);
    }
#pragma unroll
    for (int off = 16; off > 0; off >>= 1)
        m = fmaxf(m, __shfl_xor_sync(0xFFFFFFFFu, m, off));

    float sum = 0.0f;
#pragma unroll
    for (int r = 0; r < 8; r++) {
        float p = expf(v[r] - m);
        v[r] = p;
        sum += p;
    }
#pragma unroll
    for (int off = 16; off > 0; off >>= 1)
        sum += __shfl_xor_sync(0xFFFFFFFFu, sum, off);

    const float inv = 1.0f / sum;
#pragma unroll
    for (int r = 0; r < 8; r++)
        row[lane + 32 * r] = v[r] * inv;
}

// ---------------------------------------------------------------------------
// PV (tf32 mma): out[b] = P[b] @ V[b], causal K truncation.
// CTA 64x64, BK=32, 128 threads. grid = (12, 4, 128).
// ---------------------------------------------------------------------------
__global__ void __launch_bounds__(128) pv_mma_kernel(float* __restrict__ out) {
    const int bn = blockIdx.x;
    const int bm = blockIdx.y;
    const int b = blockIdx.z;

    __shared__ uint32_t Ps[64][36];
    __shared__ uint32_t Vs[32][72];

    const float* __restrict__ P = g_S + (size_t)b * TLEN * TLEN;
    const float* __restrict__ V = g_v + (size_t)b * TLEN * CDIM;

    const int tid = threadIdx.x;
    const int wid = tid >> 5, lane = tid & 31;
    const int wm = (wid & 1) * 32;
    const int wn = (wid >> 1) * 32;
    const int lr = lane >> 2, lc = lane & 3;

    float acc[2][4][4] = {};
    const int nchunk = (bm + 1) * 2;

    for (int kt = 0; kt < nchunk; kt++) {
        float4 pv[4], vv[4];
#pragma unroll
        for (int i = 0; i < 4; i++) {
            int f = tid + i * 128;
            pv[i] = *(const float4*)(P + (size_t)(bm * 64 + (f >> 3)) * TLEN + kt * 32 + (f & 7) * 4);
            vv[i] = *(const float4*)(V + (size_t)(kt * 32 + (f >> 4)) * CDIM + bn * 64 + (f & 15) * 4);
        }
        __syncthreads();
#pragma unroll
        for (int i = 0; i < 4; i++) {
            int f = tid + i * 128;
            int pr = f >> 3, pc = (f & 7) * 4;
            Ps[pr][pc + 0] = f2tf(pv[i].x); Ps[pr][pc + 1] = f2tf(pv[i].y);
            Ps[pr][pc + 2] = f2tf(pv[i].z); Ps[pr][pc + 3] = f2tf(pv[i].w);
            int vr = f >> 4, vc = (f & 15) * 4;
            Vs[vr][vc + 0] = f2tf(vv[i].x); Vs[vr][vc + 1] = f2tf(vv[i].y);
            Vs[vr][vc + 2] = f2tf(vv[i].z); Vs[vr][vc + 3] = f2tf(vv[i].w);
        }
        __syncthreads();
#pragma unroll
        for (int ks = 0; ks < 4; ks++) {
            uint32_t a[2][4], bfr[4][2];
#pragma unroll
            for (int mi = 0; mi < 2; mi++) {
                int r = wm + mi * 16 + lr;
                a[mi][0] = Ps[r][ks * 8 + lc];
                a[mi][1] = Ps[r + 8][ks * 8 + lc];
                a[mi][2] = Ps[r][ks * 8 + lc + 4];
                a[mi][3] = Ps[r + 8][ks * 8 + lc + 4];
            }
#pragma unroll
            for (int ni = 0; ni < 4; ni++) {
                int c = wn + ni * 8 + lr;
                bfr[ni][0] = Vs[ks * 8 + lc][c];
                bfr[ni][1] = Vs[ks * 8 + lc + 4][c];
            }
#pragma unroll
            for (int mi = 0; mi < 2; mi++)
#pragma unroll
                for (int ni = 0; ni < 4; ni++)
                    mma_tf32(acc[mi][ni], a[mi], bfr[ni]);
        }
    }

    float* __restrict__ op = out + (size_t)b * TLEN * CDIM;
#pragma unroll
    for (int mi = 0; mi < 2; mi++)
#pragma unroll
        for (int half = 0; half < 2; half++) {
            int r = bm * 64 + wm + mi * 16 + lr + half * 8;
#pragma unroll
            for (int ni = 0; ni < 4; ni++) {
                int c = bn * 64 + wn + ni * 8 + 2 * lc;
                *(float2*)(op + (size_t)r * CDIM + c) =
                    make_float2(acc[mi][ni][half * 2], acc[mi][ni][half * 2 + 1]);
            }
        }
}

// ---------------------------------------------------------------------------
extern "C" void kernel_launch(void* const* d_in, const int* in_sizes, int n_in,
                              void* d_out, int out_size) {
    const float* x  = (const float*)d_in[0];
    const float* Wq = (const float*)d_in[1];
    const float* Wk = (const float*)d_in[2];
    const float* Wv = (const float*)d_in[3];
    float* out = (float*)d_out;

    cudaFuncSetAttribute(qkv_mma_kernel, cudaFuncAttributeMaxDynamicSharedMemorySize, QSMEM);

    rope_table_kernel<<<(TLEN * HALF + 255) / 256, 256>>>();
    convert_x_kernel<<<(int)((size_t)MROWS * CDIM / 8 / 256), 256>>>(x);
    convert_w_kernel<<<dim3(CDIM / 32, CDIM / 32, 3), dim3(32, 8)>>>(Wq, Wk, Wv);
    qkv_mma_kernel<<<dim3(CDIM / 128, 3, MROWS / 128), 256, QSMEM>>>(x);
    scores_mma_kernel<<<dim3(TLEN / 64, TLEN / 64, BATCH), 128>>>();
    softmax_kernel<<<(MROWS * 32) / 256, 256>>>();
    pv_mma_kernel<<<dim3(CDIM / 64, TLEN / 64, BATCH), 128>>>(out);
}